// round 16
// baseline (speedup 1.0000x reference)
#include <cuda_runtime.h>
#include <cstdint>
#include <cstddef>

#define NS 512
#define NB 1024
#define NT 64

__device__ float g_partial[NB];
__device__ unsigned int g_ctr = 0;

typedef unsigned long long u64;

__device__ __forceinline__ u64 pack2(float lo, float hi) {
    u64 r; asm("mov.b64 %0, {%1, %2};" : "=l"(r) : "f"(lo), "f"(hi)); return r;
}
__device__ __forceinline__ void unpack2(u64 v, float& lo, float& hi) {
    asm("mov.b64 {%0, %1}, %2;" : "=f"(lo), "=f"(hi) : "l"(v));
}
__device__ __forceinline__ void fma2(u64& acc, u64 a, u64 b) {
    asm("fma.rn.f32x2 %0, %1, %2, %0;" : "+l"(acc) : "l"(a), "l"(b));
}
__device__ __forceinline__ u64 add2(u64 a, u64 b) {
    u64 r; asm("add.rn.f32x2 %0, %1, %2;" : "=l"(r) : "l"(a), "l"(b)); return r;
}
__device__ __forceinline__ float frcp(float x) {
    float r; asm("rcp.approx.f32 %0, %1;" : "=f"(r) : "f"(x)); return r;
}
// exp(x) * 2^-6 as one FFMA + one MUFU.EX2
__device__ __forceinline__ float expm6(float x) {
    return exp2f(fmaf(x, 1.4426950408889634f, -6.0f));
}
__device__ __forceinline__ void cp_async4(void* smem_dst, const void* gsrc) {
    unsigned s = (unsigned)__cvta_generic_to_shared(smem_dst);
    asm volatile("cp.async.ca.shared.global [%0], [%1], 4;" :: "r"(s), "l"(gsrc));
}
#define CP_COMMIT() asm volatile("cp.async.commit_group;" ::: "memory")
#define CP_WAIT(n)  asm volatile("cp.async.wait_group %0;" :: "n"(n) : "memory")

__global__ void __launch_bounds__(64)
crf_kernel(const float* __restrict__ em,
           const float* __restrict__ trans,
           const float* __restrict__ start_t,
           const float* __restrict__ end_t,
           const int* __restrict__ tags,
           const int* __restrict__ mask,
           float* __restrict__ out) {
    __shared__ __align__(16) float qsm[2][NT];     // q[j] = y_j, double-buffered
    __shared__ __align__(16) float emring[8][NT];
    __shared__ float wsum[2];
    __shared__ int   is_last;

    const int tid  = threadIdx.x;        // 0..63, one block = one chain
    const int w    = tid >> 5;
    const int lane = tid & 31;
    const int b    = blockIdx.x;
    const int col  = tid;                // my single output column
    const size_t SSTR = (size_t)NB * NT;

    // ---------------- numerator: gold-path score (computed redundantly per warp) ------
    float sc = 0.f;
    int msum = 0;
    {
#pragma unroll
        for (int k = 0; k < 16; k++) {
            int s = 1 + lane + (k << 5);
            if (s < NS) {
                int tp = tags[(s - 1) * NB + b];
                int tc = tags[s * NB + b];
                int mv = mask[s * NB + b];
                float term = trans[tp * NT + tc] + em[((size_t)s * NB + b) * NT + tc];
                sc += term * (float)mv;
                msum += mv;
            }
        }
#pragma unroll
        for (int off = 16; off; off >>= 1) {
            sc   += __shfl_xor_sync(0xffffffffu, sc, off);
            msum += __shfl_xor_sync(0xffffffffu, msum, off);
        }
        int t0 = tags[b];
        sc += start_t[t0] + em[(size_t)b * NT + t0];
        int seq_end = mask[b] + msum - 1;
        int lt = tags[(size_t)seq_end * NB + b];
        sc += end_t[lt];
    }

    // ---------------- mask bitset (per warp-lane: steps 16*lane..16*lane+15) ----------
    unsigned mbits = 0;
#pragma unroll
    for (int k = 0; k < 16; k++) {
        int s = 16 * lane + k;
        mbits |= (unsigned)(mask[s * NB + b] & 1) << k;
    }

    // ---------------- cp.async em pipeline: each lane copies its own 4B ----------------
    const float* emcol = em + (size_t)b * NT + col;
#pragma unroll
    for (int t = 1; t <= 8; t++) {
        cp_async4(&emring[t & 7][col], emcol + (size_t)t * SSTR);
        CP_COMMIT();
    }

    // ---------------- E row-pairs for my column: E[i] = {e(2i,col), e(2i+1,col)} ------
    u64 E[32];
#pragma unroll
    for (int i = 0; i < 32; i++) {
        float e0 = __expf(trans[(2 * i) * NT + col]);
        float e1 = __expf(trans[(2 * i + 1) * NT + col]);
        E[i] = pack2(e0, e1);
    }

    // ---------------- init recursion state ----------------
    float y = __expf(start_t[col] + emcol[0]);
    qsm[1][col] = y;                     // step 1 reads parity 1
    float Mtot = 0.f;                    // uniform across all 64 threads

    float eem;                           // exp(em[s]) * 2^-6 for current step
    {
        CP_WAIT(7);
        eem = expm6(emring[1][col]);     // self-copied data
    }
    __syncthreads();                     // q0 visible to both warps

// One forward step. P = parity (compile-time), RN = fused renormalization.
#define CRF_STEP(S, P, RN)                                                         \
    {                                                                              \
        const ulonglong2* q2 = reinterpret_cast<const ulonglong2*>(qsm[P]);        \
        u64 a0 = 0, a1 = 0, a2 = 0, a3 = 0;                                        \
        u64 a4 = 0, a5 = 0, a6 = 0, a7 = 0;                                        \
        _Pragma("unroll")                                                          \
        for (int m = 0; m < 4; m++) {                                              \
            ulonglong2 qA = q2[2 * m];                                             \
            ulonglong2 qB = q2[2 * m + 1];                                         \
            fma2(a0, qA.x, E[4 * m]);     fma2(a1, qA.y, E[4 * m + 1]);            \
            fma2(a2, qB.x, E[4 * m + 2]); fma2(a3, qB.y, E[4 * m + 3]);            \
        }                                                                          \
        _Pragma("unroll")                                                          \
        for (int m = 4; m < 8; m++) {                                              \
            ulonglong2 qA = q2[2 * m];                                             \
            ulonglong2 qB = q2[2 * m + 1];                                         \
            fma2(a4, qA.x, E[4 * m]);     fma2(a5, qA.y, E[4 * m + 1]);            \
            fma2(a6, qB.x, E[4 * m + 2]); fma2(a7, qB.y, E[4 * m + 3]);            \
        }                                                                          \
        u64 A = add2(add2(add2(a0, a1), add2(a2, a3)),                             \
                     add2(add2(a4, a5), add2(a6, a7)));                            \
        float lo, hi; unpack2(A, lo, hi);                                          \
        float t = lo + hi;                                                         \
        int mk = (int)((mword >> ((S) & 15)) & 1u);                                \
        if (RN) {                                                                  \
            float f = qsm[P][0];          /* uniform: y[0] of previous step */     \
            float rf = frcp(f);                                                    \
            float ycand = t * (eem * rf);                                          \
            float yold  = y * rf;                                                  \
            y = mk ? ycand : yold;                                                 \
            Mtot += __logf(f);                                                     \
        } else {                                                                   \
            float ycand = t * eem;                                                 \
            if (mk) y = ycand;                                                     \
        }                                                                          \
        qsm[(P) ^ 1][col] = y;                                                     \
        __syncthreads();                                                           \
        CP_WAIT(6);                                                                \
        eem = expm6(emring[((S) + 1) & 7][col]);                                   \
        int tt = ((S) + 8 < NS) ? ((S) + 8) : (NS - 1);                            \
        cp_async4(&emring[((S) + 8) & 7][col], emcol + (size_t)tt * SSTR);         \
        CP_COMMIT();                                                               \
    }

    // prologue: steps 1..7, renorm at step 7
    unsigned mword = __shfl_sync(0xffffffffu, mbits, 0);
    CRF_STEP(1, 1, false)
    CRF_STEP(2, 0, false)
    CRF_STEP(3, 1, false)
    CRF_STEP(4, 0, false)
    CRF_STEP(5, 1, false)
    CRF_STEP(6, 0, false)
    CRF_STEP(7, 1, true)

    // main: 63 blocks of 8 steps, renorm fused into last step of each block
    for (int o = 1; o < 64; o++) {
        const int s0 = o << 3;
        mword = __shfl_sync(0xffffffffu, mbits, o >> 1);
        CRF_STEP(s0,     0, false)
        CRF_STEP(s0 + 1, 1, false)
        CRF_STEP(s0 + 2, 0, false)
        CRF_STEP(s0 + 3, 1, false)
        CRF_STEP(s0 + 4, 0, false)
        CRF_STEP(s0 + 5, 1, false)
        CRF_STEP(s0 + 6, 0, false)
        CRF_STEP(s0 + 7, 1, true)
    }
#undef CRF_STEP

    // ---------------- normalizer = Mtot + msum*log(64) + log(sum_j y_j e^{end_j}) ------
    {
        float v = y * __expf(end_t[col]);
#pragma unroll
        for (int off = 16; off; off >>= 1)
            v += __shfl_xor_sync(0xffffffffu, v, off);
        if (lane == 0) wsum[w] = v;
        __syncthreads();
        if (tid == 0) {
            const float LOG64 = 4.1588830833596715f;
            float vs = wsum[0] + wsum[1];
            g_partial[b] = sc - (Mtot + (float)msum * LOG64 + __logf(vs));
            __threadfence();
        }
    }

    // ---------------- merged deterministic final reduction (last block) ----------------
    __syncthreads();
    if (tid == 0) {
        unsigned int old = atomicAdd(&g_ctr, 1);
        is_last = (old == (unsigned int)(gridDim.x - 1));
    }
    __syncthreads();
    if (is_last) {
        __threadfence();
        float s = 0.f;
#pragma unroll
        for (int i = 0; i < NB / 64; i++)
            s += g_partial[tid + i * 64];
#pragma unroll
        for (int off = 16; off; off >>= 1)
            s += __shfl_xor_sync(0xffffffffu, s, off);
        if (lane == 0) wsum[w] = s;
        __syncthreads();
        if (tid == 0) { out[0] = wsum[0] + wsum[1]; g_ctr = 0; }
    }
}

extern "C" void kernel_launch(void* const* d_in, const int* in_sizes, int n_in,
                              void* d_out, int out_size) {
    const float* em    = (const float*)d_in[0];
    const float* trans = (const float*)d_in[1];
    const float* st    = (const float*)d_in[2];
    const float* et    = (const float*)d_in[3];
    const int*   tags  = (const int*)d_in[4];
    const int*   mask  = (const int*)d_in[5];

    crf_kernel<<<NB, 64>>>(em, trans, st, et, tags, mask, (float*)d_out);
}

// round 17
// speedup vs baseline: 1.2057x; 1.2057x over previous
#include <cuda_runtime.h>
#include <cstdint>
#include <cstddef>

#define NS 512
#define NB 1024
#define NT 64

__device__ float g_partial[NB];
__device__ unsigned int g_ctr = 0;

typedef unsigned long long u64;

__device__ __forceinline__ u64 pack2(float lo, float hi) {
    u64 r; asm("mov.b64 %0, {%1, %2};" : "=l"(r) : "f"(lo), "f"(hi)); return r;
}
__device__ __forceinline__ void unpack2(u64 v, float& lo, float& hi) {
    asm("mov.b64 {%0, %1}, %2;" : "=f"(lo), "=f"(hi) : "l"(v));
}
__device__ __forceinline__ void fma2(u64& acc, u64 a, u64 b) {
    asm("fma.rn.f32x2 %0, %1, %2, %0;" : "+l"(acc) : "l"(a), "l"(b));
}
__device__ __forceinline__ u64 add2(u64 a, u64 b) {
    u64 r; asm("add.rn.f32x2 %0, %1, %2;" : "=l"(r) : "l"(a), "l"(b)); return r;
}
__device__ __forceinline__ u64 mul2(u64 a, u64 b) {
    u64 r; asm("mul.rn.f32x2 %0, %1, %2;" : "=l"(r) : "l"(a), "l"(b)); return r;
}
__device__ __forceinline__ float frcp(float x) {
    float r; asm("rcp.approx.f32 %0, %1;" : "=f"(r) : "f"(x)); return r;
}
// exp(x) * 2^-6 as one FFMA + one MUFU.EX2
__device__ __forceinline__ float expm6(float x) {
    return exp2f(fmaf(x, 1.4426950408889634f, -6.0f));
}
__device__ __forceinline__ void sts64(u64* p, u64 v) {
    asm volatile("st.shared.b64 [%0], %1;" :: "l"(p), "l"(v) : "memory");
}
__device__ __forceinline__ void cp_async8(void* smem_dst, const void* gsrc) {
    unsigned s = (unsigned)__cvta_generic_to_shared(smem_dst);
    asm volatile("cp.async.ca.shared.global [%0], [%1], 8;" :: "r"(s), "l"(gsrc));
}
#define CP_COMMIT() asm volatile("cp.async.commit_group;" ::: "memory")
#define CP_WAIT(n)  asm volatile("cp.async.wait_group %0;" :: "n"(n) : "memory")

__global__ void __launch_bounds__(32)
crf_kernel(const float* __restrict__ em,
           const float* __restrict__ trans,
           const float* __restrict__ start_t,
           const float* __restrict__ end_t,
           const int* __restrict__ tags,
           const int* __restrict__ mask,
           float* __restrict__ out) {
    __shared__ __align__(16) u64   qsm[2][32];       // slot l = {y_{2l}, y_{2l+1}}
    __shared__ __align__(16) float emring[32][NT];   // 32-step ring, 8 KB

    const int lane = threadIdx.x;        // one warp = one chain
    const int b    = blockIdx.x;
    const int c0   = 2 * lane;           // my two columns: c0, c0+1
    const size_t SSTR = (size_t)NB * NT;

    // ---------------- numerator: gold-path score ----------------
    float sc = 0.f;
    int msum = 0;
    {
#pragma unroll
        for (int k = 0; k < 16; k++) {
            int s = 1 + lane + (k << 5);
            if (s < NS) {
                int tp = tags[(s - 1) * NB + b];
                int tc = tags[s * NB + b];
                int mv = mask[s * NB + b];
                float term = trans[tp * NT + tc] + em[((size_t)s * NB + b) * NT + tc];
                sc += term * (float)mv;
                msum += mv;
            }
        }
#pragma unroll
        for (int off = 16; off; off >>= 1) {
            sc   += __shfl_xor_sync(0xffffffffu, sc, off);
            msum += __shfl_xor_sync(0xffffffffu, msum, off);
        }
        int t0 = tags[b];
        sc += start_t[t0] + em[(size_t)b * NT + t0];
        int seq_end = mask[b] + msum - 1;
        int lt = tags[(size_t)seq_end * NB + b];
        sc += end_t[lt];
    }

    // ---------------- mask bitset: lane l holds bits for steps 16l..16l+15 ----------
    unsigned mbits = 0;
#pragma unroll
    for (int k = 0; k < 16; k++) {
        int s = 16 * lane + k;
        mbits |= (unsigned)(mask[s * NB + b] & 1) << k;
    }

    // ---------------- cp.async em pipeline: 4 groups covering steps 1..31 -------------
    const float* emb2l = em + (size_t)b * NT + c0;   // lane's own 8B per step
#pragma unroll
    for (int t = 1; t <= 7; t++)
        cp_async8(&emring[t][c0], emb2l + (size_t)t * SSTR);
    CP_COMMIT();                                     // G0: steps 1-7
#pragma unroll
    for (int t = 8; t <= 15; t++)
        cp_async8(&emring[t][c0], emb2l + (size_t)t * SSTR);
    CP_COMMIT();                                     // G1: steps 8-15
#pragma unroll
    for (int t = 16; t <= 23; t++)
        cp_async8(&emring[t][c0], emb2l + (size_t)t * SSTR);
    CP_COMMIT();                                     // G2: steps 16-23
#pragma unroll
    for (int t = 24; t <= 31; t++)
        cp_async8(&emring[t][c0], emb2l + (size_t)t * SSTR);
    CP_COMMIT();                                     // G3: steps 24-31

    // ---------------- E row-pair packed: EC<j>[i] = {E[2i][c0+j], E[2i+1][c0+j]} ------
    u64 EC0[32], EC1[32];
#pragma unroll
    for (int i = 0; i < 32; i++) {
        float2 ta = *reinterpret_cast<const float2*>(trans + (2 * i) * NT + c0);
        float2 tb = *reinterpret_cast<const float2*>(trans + (2 * i + 1) * NT + c0);
        EC0[i] = pack2(__expf(ta.x), __expf(tb.x));
        EC1[i] = pack2(__expf(ta.y), __expf(tb.y));
    }

    // ---------------- init recursion state ----------------
    u64 y01;
    {
        float2 e0 = *reinterpret_cast<const float2*>(emb2l);
        float2 s2 = *reinterpret_cast<const float2*>(start_t + c0);
        y01 = pack2(__expf(s2.x + e0.x), __expf(s2.y + e0.y));
        sts64(&qsm[1][lane], y01);
    }
    float Mtot = 0.f;                            // renorm log accumulator (uniform)

    u64 eem01;                                   // exp(em[s]) * 2^-6 for current step
    {
        CP_WAIT(2);                              // G0, G1 resident
        float2 e1 = *reinterpret_cast<const float2*>(&emring[1][c0]);
        eem01 = pack2(expm6(e1.x), expm6(e1.y));
    }
    __syncwarp();

// One forward step. No per-step memory-pipeline ops.
// P = parity (compile-time), RN = fused renormalization.
#define CRF_STEP(S, P, RN)                                                         \
    {                                                                              \
        const ulonglong2* q2 = reinterpret_cast<const ulonglong2*>(qsm[P]);        \
        u64 a0 = 0, a1 = 0, a2 = 0, a3 = 0;                                        \
        u64 a4 = 0, a5 = 0, a6 = 0, a7 = 0;                                        \
        _Pragma("unroll")                                                          \
        for (int m = 0; m < 8; m++) {                                              \
            ulonglong2 qA = q2[2 * m];                                             \
            ulonglong2 qB = q2[2 * m + 1];                                         \
            fma2(a0, qA.x, EC0[4 * m]);     fma2(a1, qA.x, EC1[4 * m]);            \
            fma2(a2, qA.y, EC0[4 * m + 1]); fma2(a3, qA.y, EC1[4 * m + 1]);        \
            fma2(a4, qB.x, EC0[4 * m + 2]); fma2(a5, qB.x, EC1[4 * m + 2]);        \
            fma2(a6, qB.y, EC0[4 * m + 3]); fma2(a7, qB.y, EC1[4 * m + 3]);        \
        }                                                                          \
        u64 A0 = add2(add2(a0, a2), add2(a4, a6));   /* col c0, row-pair packed */ \
        u64 A1 = add2(add2(a1, a3), add2(a5, a7));   /* col c0+1 */                \
        float lo0, hi0, lo1, hi1;                                                  \
        unpack2(A0, lo0, hi0);                                                     \
        unpack2(A1, lo1, hi1);                                                     \
        int mk = (int)((mword >> ((S) & 15)) & 1u);                                \
        u64 cnew = mul2(pack2(lo0 + hi0, lo1 + hi1), eem01);                       \
        if (mk) y01 = cnew;                                                        \
        if (RN) {                                                                  \
            float f0, fx; unpack2(y01, f0, fx);                                    \
            float f = __shfl_sync(0xffffffffu, f0, 0);                             \
            float rf = frcp(f);                                                    \
            y01 = mul2(y01, pack2(rf, rf));                                        \
            Mtot += __logf(f);                                                     \
        }                                                                          \
        sts64(&qsm[(P) ^ 1][lane], y01);                                           \
        __syncwarp();                                                              \
        float2 en = *reinterpret_cast<const float2*>(&emring[((S) + 1) & 31][c0]); \
        eem01 = pack2(expm6(en.x), expm6(en.y));                                   \
    }

    // prologue: steps 1..7, renorm at step 7
    unsigned mword = __shfl_sync(0xffffffffu, mbits, 0);
    CRF_STEP(1, 1, false)
    CRF_STEP(2, 0, false)
    CRF_STEP(3, 1, false)
    CRF_STEP(4, 0, false)
    CRF_STEP(5, 1, false)
    CRF_STEP(6, 0, false)
    CRF_STEP(7, 1, true)

    // main: 63 blocks of 8 steps; batched prefetch + wait at block start,
    // renorm fused into last step of each block.
    for (int o = 1; o < 64; o++) {
        const int s0 = o << 3;
        // prefetch group o+3 (steps 8(o+3)..8(o+3)+7); slot from unclamped index
        {
            const int base = (o + 3) << 3;
#pragma unroll
            for (int j = 0; j < 8; j++) {
                int tt = base + j;
                int src = (tt < NS) ? tt : (NS - 1);
                cp_async8(&emring[tt & 31][c0], emb2l + (size_t)src * SSTR);
            }
            CP_COMMIT();
            CP_WAIT(2);    // group o+1 resident (covers this block + end-of-block read)
        }
        mword = __shfl_sync(0xffffffffu, mbits, o >> 1);
        CRF_STEP(s0,     0, false)
        CRF_STEP(s0 + 1, 1, false)
        CRF_STEP(s0 + 2, 0, false)
        CRF_STEP(s0 + 3, 1, false)
        CRF_STEP(s0 + 4, 0, false)
        CRF_STEP(s0 + 5, 1, false)
        CRF_STEP(s0 + 6, 0, false)
        CRF_STEP(s0 + 7, 1, true)
    }
#undef CRF_STEP

    // ---------------- normalizer = Mtot + msum*log(64) + log(sum_j y_j e^{end_j}) ------
    {
        float2 e2 = *reinterpret_cast<const float2*>(end_t + c0);
        float y0, y1; unpack2(y01, y0, y1);
        float v = y0 * __expf(e2.x) + y1 * __expf(e2.y);
#pragma unroll
        for (int off = 16; off; off >>= 1)
            v += __shfl_xor_sync(0xffffffffu, v, off);
        if (lane == 0) {
            const float LOG64 = 4.1588830833596715f;
            g_partial[b] = sc - (Mtot + (float)msum * LOG64 + __logf(v));
            __threadfence();
        }
    }

    // ---------------- merged deterministic final reduction (last block) ----------------
    __syncwarp();
    int last = 0;
    if (lane == 0) {
        unsigned int old = atomicAdd(&g_ctr, 1);
        last = (old == (unsigned int)(gridDim.x - 1));
    }
    last = __shfl_sync(0xffffffffu, last, 0);
    if (last) {
        __threadfence();
        float s = 0.f;
#pragma unroll
        for (int i = 0; i < NB / 32; i++)
            s += g_partial[lane + i * 32];
#pragma unroll
        for (int off = 16; off; off >>= 1)
            s += __shfl_xor_sync(0xffffffffu, s, off);
        if (lane == 0) { out[0] = s; g_ctr = 0; }
    }
}

extern "C" void kernel_launch(void* const* d_in, const int* in_sizes, int n_in,
                              void* d_out, int out_size) {
    const float* em    = (const float*)d_in[0];
    const float* trans = (const float*)d_in[1];
    const float* st    = (const float*)d_in[2];
    const float* et    = (const float*)d_in[3];
    const int*   tags  = (const int*)d_in[4];
    const int*   mask  = (const int*)d_in[5];

    crf_kernel<<<NB, 32>>>(em, trans, st, et, tags, mask, (float*)d_out);
}